// round 16
// baseline (speedup 1.0000x reference)
#include <cuda_runtime.h>
#include <cuda_fp16.h>
#include <cstdint>

#define B_DIM 128
#define L_DIM 12
#define F_DIM 4096
#define A_DIM 768
#define PAIRS 78
#define NTILES (PAIRS * 6)        // 468
#define NFULL_T 304               // full-K tiles
#define NQT (NTILES - NFULL_T)    // 164 quartered tiles
#define NUNITS (NFULL_T + NQT * 4)   // 960
#define THREADS 256
#define BK 64
#define STAGE_BYTES 32768
#define SMEM_BYTES (2 * STAGE_BYTES + 16)

__device__ __half g_s1[(size_t)NFULL_T * 16384];      // full tiles [t][b][aloc] fp16
__device__ __half g_s2[(size_t)NQT * 4 * 16384];      // quarters   [u][b][aloc] fp16
__device__ __half g_xf16[(size_t)B_DIM * L_DIM * F_DIM];
__device__ int    g_ctr;

struct WPtrs { const float* w[12]; };
struct Cur { const float* wgp; const __half* xl; __half* outp; int nch; };

__device__ __forceinline__ uint32_t smem_u32(const void* p) {
    uint32_t a;
    asm("{ .reg .u64 t; cvta.to.shared.u64 t, %1; cvt.u32.u64 %0, t; }"
        : "=r"(a) : "l"(p));
    return a;
}
__device__ __forceinline__ void cp16(uint32_t s, const void* g) {
    asm volatile("cp.async.cg.shared.global [%0], [%1], 16;" :: "r"(s), "l"(g));
}
__device__ __forceinline__ uint32_t pack2(float a, float b) {
    __half2 h = __floats2half2_rn(a, b);
    return *reinterpret_cast<uint32_t*>(&h);
}
__device__ __forceinline__ void pfL2(const float* p) {
    asm volatile("prefetch.global.L2 [%0];" :: "l"(p));
}

// ---------------- x pre-convert to fp16 (+ counter reset), 32B/thread ----------------
__global__ __launch_bounds__(256)
void cvt_x_kernel(const float* __restrict__ x) {
    if (blockIdx.x == 0 && threadIdx.x == 0) g_ctr = 0;
    int idx = blockIdx.x * blockDim.x + threadIdx.x;
    const int n8 = (B_DIM * L_DIM * F_DIM) / 8;
    if (idx >= n8) return;
    float4 v0 = reinterpret_cast<const float4*>(x)[2 * idx];
    float4 v1 = reinterpret_cast<const float4*>(x)[2 * idx + 1];
    uint4 o;
    o.x = pack2(v0.x, v0.y);
    o.y = pack2(v0.z, v0.w);
    o.z = pack2(v1.x, v1.y);
    o.w = pack2(v1.z, v1.w);
    reinterpret_cast<uint4*>(g_xf16)[idx] = o;
}

// ---------------- persistent GEMM, 2-stage ring + W L2 prefetch + 4x8 W batches ----------------
__global__ __launch_bounds__(THREADS, 2)
void gemm_pair_kernel(WPtrs wp) {
    extern __shared__ char smem[];
    const uint32_t smb = smem_u32(smem);
    int* sGrab = reinterpret_cast<int*>(smem + 2 * STAGE_BYTES);
    const int tid  = threadIdx.x;
    const int lane = tid & 31;
    const int warp = tid >> 5;
    const int wm = (warp >> 2) * 64;
    const int wn = (warp & 3) * 32;
    const int wn_idx = tid & 127;
    const int wkb    = (tid >> 7) * 32;

    auto decode = [&](Cur& U, int u) -> bool {
        if (u >= NUNITS) return false;
        int tile, k0c;
        if (u < NFULL_T) {
            tile = u; k0c = 0; U.nch = 64;
            U.outp = g_s1 + (size_t)u * 16384;
        } else {
            int q = u - NFULL_T;
            tile = NFULL_T + (q >> 2); k0c = (q & 3) * 16; U.nch = 16;
            U.outp = g_s2 + (size_t)q * 16384;
        }
        int p = tile / 6, ntc = tile - p * 6;
        int i = 0, base = 0;
        while (p >= base + i + 1) { base += i + 1; i++; }
        int l = p - base;
        U.wgp = wp.w[i] + (size_t)l * F_DIM * A_DIM + ntc * 128 + wn_idx
              + (size_t)(k0c * BK) * A_DIM;
        U.xl  = g_xf16 + (size_t)l * F_DIM + k0c * BK;
        return true;
    };

    auto stage_x = [&](uint32_t xb, const __half* xg) {
        #pragma unroll
        for (int j = 0; j < 4; j++) {
            int cid = tid + j * 256;
            int m = cid >> 3, c = cid & 7;
            cp16(xb + (uint32_t)(m * 128 + ((c ^ (m & 7)) << 4)),
                 xg + (size_t)m * (L_DIM * F_DIM) + c * 8);
        }
    };
    // W loads in 4 batches of 8 rows
    auto ldg_w8 = [&](const float* wgp, int kel, int b8, float (&wv)[8]) {
        const float* g = wgp + (size_t)(kel + wkb + b8 * 8) * A_DIM;
        #pragma unroll
        for (int j = 0; j < 8; j++) wv[j] = __ldg(g + (size_t)j * A_DIM);
    };
    auto sts_w8 = [&](uint32_t sb, int b8, const float (&wv)[8]) {
        uint32_t rowb = sb + 16384 + wn_idx * 128;
        uint32_t q = (uint32_t)((wkb >> 3) + b8);
        uint32_t addr = rowb + ((q ^ (uint32_t)(wn_idx & 7)) << 4);
        uint32_t r0 = pack2(wv[0], wv[1]);
        uint32_t r1 = pack2(wv[2], wv[3]);
        uint32_t r2 = pack2(wv[4], wv[5]);
        uint32_t r3 = pack2(wv[6], wv[7]);
        asm volatile("st.shared.v4.b32 [%0], {%1,%2,%3,%4};"
                     :: "r"(addr), "r"(r0), "r"(r1), "r"(r2), "r"(r3) : "memory");
    };

    float acc[4][4][4];
    auto zero_acc = [&]() {
        #pragma unroll
        for (int q = 0; q < 4; q++)
            #pragma unroll
            for (int r = 0; r < 4; r++)
                #pragma unroll
                for (int s = 0; s < 4; s++) acc[q][r][s] = 0.f;
    };

    auto compute_kk = [&](uint32_t abase, int kk) {
        uint32_t btbase = abase + 16384;
        uint32_t a[4][4];
        #pragma unroll
        for (int mt = 0; mt < 4; mt++) {
            int m = wm + mt * 16 + (lane & 15);
            int c = kk * 2 + (lane >> 4);
            uint32_t addr = abase + (uint32_t)(m * 128 + ((c ^ (m & 7)) << 4));
            asm volatile(
                "ldmatrix.sync.aligned.m8n8.x4.shared.b16 {%0,%1,%2,%3}, [%4];"
                : "=r"(a[mt][0]), "=r"(a[mt][1]), "=r"(a[mt][2]), "=r"(a[mt][3])
                : "r"(addr));
        }
        uint32_t b[4][2];
        #pragma unroll
        for (int g2 = 0; g2 < 2; g2++) {
            int nrow = wn + (2 * g2 + (lane >> 4)) * 8 + (lane & 7);
            int c16  = kk * 2 + ((lane >> 3) & 1);
            uint32_t addr = btbase + (uint32_t)(nrow * 128 + ((c16 ^ (nrow & 7)) << 4));
            asm volatile(
                "ldmatrix.sync.aligned.m8n8.x4.shared.b16 {%0,%1,%2,%3}, [%4];"
                : "=r"(b[2*g2][0]), "=r"(b[2*g2][1]),
                  "=r"(b[2*g2+1][0]), "=r"(b[2*g2+1][1])
                : "r"(addr));
        }
        #pragma unroll
        for (int mt = 0; mt < 4; mt++)
            #pragma unroll
            for (int nt = 0; nt < 4; nt++) {
                asm volatile(
                    "mma.sync.aligned.m16n8k16.row.col.f32.f16.f16.f32 "
                    "{%0,%1,%2,%3}, {%4,%5,%6,%7}, {%8,%9}, {%0,%1,%2,%3};"
                    : "+f"(acc[mt][nt][0]), "+f"(acc[mt][nt][1]),
                      "+f"(acc[mt][nt][2]), "+f"(acc[mt][nt][3])
                    : "r"(a[mt][0]), "r"(a[mt][1]), "r"(a[mt][2]), "r"(a[mt][3]),
                      "r"(b[nt][0]), "r"(b[nt][1]));
            }
    };

    auto epilogue = [&](__half* outp) {
        #pragma unroll
        for (int mt = 0; mt < 4; mt++) {
            int r0 = wm + mt * 16 + (lane >> 2);
            #pragma unroll
            for (int nt = 0; nt < 4; nt++) {
                int cc = wn + nt * 8 + 2 * (lane & 3);
                uint32_t v0 = pack2(acc[mt][nt][0], acc[mt][nt][1]);
                uint32_t v1 = pack2(acc[mt][nt][2], acc[mt][nt][3]);
                *reinterpret_cast<uint32_t*>(outp + (size_t)r0 * 128 + cc) = v0;
                *reinterpret_cast<uint32_t*>(outp + (size_t)(r0 + 8) * 128 + cc) = v1;
            }
        }
    };

    // ---- initial grab + prologue (stage chunk 0 into stage A) ----
    if (tid == 0) sGrab[0] = atomicAdd(&g_ctr, 1);
    __syncthreads();
    Cur cur;
    if (!decode(cur, sGrab[0])) return;

    uint32_t sA = smb, sB = smb + STAGE_BYTES;
    {
        float wv[8];
        stage_x(sA, cur.xl);
        asm volatile("cp.async.commit_group;");
        if (cur.nch > 1)
            pfL2(cur.wgp + (size_t)(BK + wkb + lane) * A_DIM);
        #pragma unroll
        for (int b8 = 0; b8 < 4; b8++) {
            ldg_w8(cur.wgp, 0, b8, wv);
            sts_w8(sA, b8, wv);
        }
    }
    zero_acc();
    int cloc = 0;
    int nxtu = NUNITS;

    for (;;) {
        asm volatile("cp.async.wait_group 0;");
        __syncthreads();

        if (cloc == cur.nch - 2) nxtu = sGrab[0];

        const bool last = (cloc == cur.nch - 1);
        Cur nxt;
        bool nv = false, stg = true;
        const float* swgp = cur.wgp;
        const __half* sxl = cur.xl;
        int skel = (cloc + 1) * BK;
        if (last) {
            nv = decode(nxt, nxtu);
            if (nv) { swgp = nxt.wgp; sxl = nxt.xl; skel = 0; }
            else stg = false;
        }

        float wv[8];
        if (stg) {
            ldg_w8(swgp, skel, 0, wv);
            stage_x(sB, sxl + skel);
            if (cloc + 2 < cur.nch) {
                pfL2(cur.wgp + (size_t)((cloc + 2) * BK + wkb + lane) * A_DIM);
            } else if (cloc == cur.nch - 2) {
                Cur t;
                if (decode(t, nxtu))
                    pfL2(t.wgp + (size_t)(wkb + lane) * A_DIM);
            } else if (last && nv && nxt.nch > 1) {
                pfL2(nxt.wgp + (size_t)(BK + wkb + lane) * A_DIM);
            }
        }
        asm volatile("cp.async.commit_group;");
        compute_kk(sA, 0);
        if (stg) { sts_w8(sB, 0, wv); ldg_w8(swgp, skel, 1, wv); }
        compute_kk(sA, 1);
        if (stg) { sts_w8(sB, 1, wv); ldg_w8(swgp, skel, 2, wv); }
        compute_kk(sA, 2);
        if (stg) { sts_w8(sB, 2, wv); ldg_w8(swgp, skel, 3, wv); }
        compute_kk(sA, 3);
        if (stg) sts_w8(sB, 3, wv);

        if (cloc == cur.nch - 3 && tid == 0)
            sGrab[0] = atomicAdd(&g_ctr, 1);

        if (last) {
            epilogue(cur.outp);
            zero_acc();
            if (!nv) break;
            cur = nxt;
            cloc = 0;
        } else {
            cloc++;
        }
        uint32_t t = sA; sA = sB; sB = t;
    }
}

// ---------------- reduction: fp16 partials -> fp32 out, 4 outputs/thread ----------------
__global__ __launch_bounds__(256)
void reduce_kernel(float* __restrict__ out) {
    int idx = blockIdx.x * blockDim.x + threadIdx.x;
    const int total4 = (B_DIM * L_DIM * A_DIM) / 4;
    if (idx >= total4) return;
    int a    = idx * 4;
    int aloc = a & 127;
    int ntc  = (a >> 7) % 6;
    int rem  = idx / (A_DIM / 4);
    int i    = rem % L_DIM;
    int b    = rem / L_DIM;
    int base = i * (i + 1) / 2;

    float4 s = make_float4(0.f, 0.f, 0.f, 0.f);
    for (int l = 0; l <= i; l++) {
        int tile = (base + l) * 6 + ntc;
        if (tile < NFULL_T) {
            uint2 v = *reinterpret_cast<const uint2*>(
                g_s1 + (size_t)tile * 16384 + (size_t)b * 128 + aloc);
            float2 f0 = __half22float2(*reinterpret_cast<__half2*>(&v.x));
            float2 f1 = __half22float2(*reinterpret_cast<__half2*>(&v.y));
            s.x += f0.x; s.y += f0.y; s.z += f1.x; s.w += f1.y;
        } else {
            const __half* pb = g_s2 + (size_t)(tile - NFULL_T) * 4 * 16384
                             + (size_t)b * 128 + aloc;
            #pragma unroll
            for (int q = 0; q < 4; q++) {
                uint2 v = *reinterpret_cast<const uint2*>(pb + (size_t)q * 16384);
                float2 f0 = __half22float2(*reinterpret_cast<__half2*>(&v.x));
                float2 f1 = __half22float2(*reinterpret_cast<__half2*>(&v.y));
                s.x += f0.x; s.y += f0.y; s.z += f1.x; s.w += f1.y;
            }
        }
    }
    size_t flat = ((size_t)b * L_DIM + i) * A_DIM + (a % A_DIM);
    *reinterpret_cast<float4*>(out + flat) = s;
}

extern "C" void kernel_launch(void* const* d_in, const int* in_sizes, int n_in,
                              void* d_out, int out_size) {
    const float* x = (const float*)d_in[0];
    WPtrs wp;
    for (int i = 0; i < 12; i++) wp.w[i] = (const float*)d_in[1 + i];

    int dev = 0;
    cudaGetDevice(&dev);
    int sms = 0;
    cudaDeviceGetAttribute(&sms, cudaDevAttrMultiProcessorCount, dev);
    int G = 2 * sms;
    if (G > NFULL_T) G = NFULL_T;
    if (G < 1) G = 1;

    cudaFuncSetAttribute(reinterpret_cast<const void*>(gemm_pair_kernel),
                         cudaFuncAttributeMaxDynamicSharedMemorySize, SMEM_BYTES);

    const int n8 = (B_DIM * L_DIM * F_DIM) / 8;
    cvt_x_kernel<<<(n8 + 255) / 256, 256>>>(x);

    gemm_pair_kernel<<<G, THREADS, SMEM_BYTES>>>(wp);

    const int total4 = (B_DIM * L_DIM * A_DIM) / 4;
    reduce_kernel<<<(total4 + 255) / 256, 256>>>((float*)d_out);
}

// round 17
// speedup vs baseline: 1.1464x; 1.1464x over previous
#include <cuda_runtime.h>
#include <cuda_fp16.h>
#include <cstdint>

#define B_DIM 128
#define L_DIM 12
#define F_DIM 4096
#define A_DIM 768
#define PAIRS 78
#define NTILES (PAIRS * 6)        // 468
#define NFULL_T 304               // full-K tiles
#define NQT (NTILES - NFULL_T)    // 164 quartered tiles
#define NUNITS (NFULL_T + NQT * 4)   // 960
#define THREADS 256
#define BK 64
#define STAGE_BYTES 32768
#define SMEM_BYTES (2 * STAGE_BYTES + 16)

__device__ __half g_s1[(size_t)NFULL_T * 16384];      // full tiles [t][b][aloc] fp16
__device__ __half g_s2[(size_t)NQT * 4 * 16384];      // quarters   [u][b][aloc] fp16
__device__ __half g_xf16[(size_t)B_DIM * L_DIM * F_DIM];
__device__ int    g_ctr;

struct WPtrs { const float* w[12]; };
struct Cur { const float* wgp; const __half* xl; __half* outp; int nch; };

__device__ __forceinline__ uint32_t smem_u32(const void* p) {
    uint32_t a;
    asm("{ .reg .u64 t; cvta.to.shared.u64 t, %1; cvt.u32.u64 %0, t; }"
        : "=r"(a) : "l"(p));
    return a;
}
__device__ __forceinline__ void cp16(uint32_t s, const void* g) {
    asm volatile("cp.async.cg.shared.global [%0], [%1], 16;" :: "r"(s), "l"(g));
}
__device__ __forceinline__ uint32_t pack2(float a, float b) {
    __half2 h = __floats2half2_rn(a, b);
    return *reinterpret_cast<uint32_t*>(&h);
}

// ---------------- x pre-convert to fp16 (+ counter reset), 32B/thread ----------------
__global__ __launch_bounds__(256)
void cvt_x_kernel(const float* __restrict__ x) {
    if (blockIdx.x == 0 && threadIdx.x == 0) g_ctr = 0;
    int idx = blockIdx.x * blockDim.x + threadIdx.x;
    const int n8 = (B_DIM * L_DIM * F_DIM) / 8;
    if (idx >= n8) return;
    float4 v0 = reinterpret_cast<const float4*>(x)[2 * idx];
    float4 v1 = reinterpret_cast<const float4*>(x)[2 * idx + 1];
    uint4 o;
    o.x = pack2(v0.x, v0.y);
    o.y = pack2(v0.z, v0.w);
    o.z = pack2(v1.x, v1.y);
    o.w = pack2(v1.z, v1.w);
    reinterpret_cast<uint4*>(g_xf16)[idx] = o;
}

// ---------------- persistent GEMM, mixed units, 2-stage ring + W L2 prefetch ----------------
__global__ __launch_bounds__(THREADS, 2)
void gemm_pair_kernel(WPtrs wp) {
    extern __shared__ char smem[];
    const uint32_t smb = smem_u32(smem);
    int* sGrab = reinterpret_cast<int*>(smem + 2 * STAGE_BYTES);
    const int tid  = threadIdx.x;
    const int lane = tid & 31;
    const int warp = tid >> 5;
    const int wm = (warp >> 2) * 64;
    const int wn = (warp & 3) * 32;
    const int wn_idx = tid & 127;
    const int wkb    = (tid >> 7) * 32;

    auto decode = [&](Cur& U, int u) -> bool {
        if (u >= NUNITS) return false;
        int tile, k0c;
        if (u < NFULL_T) {
            tile = u; k0c = 0; U.nch = 64;
            U.outp = g_s1 + (size_t)u * 16384;
        } else {
            int q = u - NFULL_T;
            tile = NFULL_T + (q >> 2); k0c = (q & 3) * 16; U.nch = 16;
            U.outp = g_s2 + (size_t)q * 16384;
        }
        int p = tile / 6, ntc = tile - p * 6;
        int i = 0, base = 0;
        while (p >= base + i + 1) { base += i + 1; i++; }
        int l = p - base;
        U.wgp = wp.w[i] + (size_t)l * F_DIM * A_DIM + ntc * 128 + wn_idx
              + (size_t)(k0c * BK) * A_DIM;
        U.xl  = g_xf16 + (size_t)l * F_DIM + k0c * BK;
        return true;
    };

    auto stage_x = [&](uint32_t xb, const __half* xg) {
        #pragma unroll
        for (int j = 0; j < 4; j++) {
            int cid = tid + j * 256;
            int m = cid >> 3, c = cid & 7;
            cp16(xb + (uint32_t)(m * 128 + ((c ^ (m & 7)) << 4)),
                 xg + (size_t)m * (L_DIM * F_DIM) + c * 8);
        }
    };
    auto ldg_w = [&](const float* wgp, int kel, int h, float (&wv)[16]) {
        const float* g = wgp + (size_t)(kel + wkb + h * 16) * A_DIM;
        #pragma unroll
        for (int j = 0; j < 16; j++) wv[j] = __ldg(g + (size_t)j * A_DIM);
    };
    auto sts_w = [&](uint32_t sb, int h, const float (&wv)[16]) {
        uint32_t rowb = sb + 16384 + wn_idx * 128;
        #pragma unroll
        for (int c2 = 0; c2 < 2; c2++) {
            uint32_t q = (uint32_t)((wkb >> 3) + h * 2 + c2);
            uint32_t addr = rowb + ((q ^ (uint32_t)(wn_idx & 7)) << 4);
            uint32_t r0 = pack2(wv[c2 * 8 + 0], wv[c2 * 8 + 1]);
            uint32_t r1 = pack2(wv[c2 * 8 + 2], wv[c2 * 8 + 3]);
            uint32_t r2 = pack2(wv[c2 * 8 + 4], wv[c2 * 8 + 5]);
            uint32_t r3 = pack2(wv[c2 * 8 + 6], wv[c2 * 8 + 7]);
            asm volatile("st.shared.v4.b32 [%0], {%1,%2,%3,%4};"
                         :: "r"(addr), "r"(r0), "r"(r1), "r"(r2), "r"(r3) : "memory");
        }
    };

    float acc[4][4][4];
    auto zero_acc = [&]() {
        #pragma unroll
        for (int q = 0; q < 4; q++)
            #pragma unroll
            for (int r = 0; r < 4; r++)
                #pragma unroll
                for (int s = 0; s < 4; s++) acc[q][r][s] = 0.f;
    };

    auto compute_kk = [&](uint32_t abase, int kk) {
        uint32_t btbase = abase + 16384;
        uint32_t a[4][4];
        #pragma unroll
        for (int mt = 0; mt < 4; mt++) {
            int m = wm + mt * 16 + (lane & 15);
            int c = kk * 2 + (lane >> 4);
            uint32_t addr = abase + (uint32_t)(m * 128 + ((c ^ (m & 7)) << 4));
            asm volatile(
                "ldmatrix.sync.aligned.m8n8.x4.shared.b16 {%0,%1,%2,%3}, [%4];"
                : "=r"(a[mt][0]), "=r"(a[mt][1]), "=r"(a[mt][2]), "=r"(a[mt][3])
                : "r"(addr));
        }
        uint32_t b[4][2];
        #pragma unroll
        for (int g2 = 0; g2 < 2; g2++) {
            int nrow = wn + (2 * g2 + (lane >> 4)) * 8 + (lane & 7);
            int c16  = kk * 2 + ((lane >> 3) & 1);
            uint32_t addr = btbase + (uint32_t)(nrow * 128 + ((c16 ^ (nrow & 7)) << 4));
            asm volatile(
                "ldmatrix.sync.aligned.m8n8.x4.shared.b16 {%0,%1,%2,%3}, [%4];"
                : "=r"(b[2*g2][0]), "=r"(b[2*g2][1]),
                  "=r"(b[2*g2+1][0]), "=r"(b[2*g2+1][1])
                : "r"(addr));
        }
        #pragma unroll
        for (int mt = 0; mt < 4; mt++)
            #pragma unroll
            for (int nt = 0; nt < 4; nt++) {
                asm volatile(
                    "mma.sync.aligned.m16n8k16.row.col.f32.f16.f16.f32 "
                    "{%0,%1,%2,%3}, {%4,%5,%6,%7}, {%8,%9}, {%0,%1,%2,%3};"
                    : "+f"(acc[mt][nt][0]), "+f"(acc[mt][nt][1]),
                      "+f"(acc[mt][nt][2]), "+f"(acc[mt][nt][3])
                    : "r"(a[mt][0]), "r"(a[mt][1]), "r"(a[mt][2]), "r"(a[mt][3]),
                      "r"(b[nt][0]), "r"(b[nt][1]));
            }
    };

    auto epilogue = [&](__half* outp) {
        #pragma unroll
        for (int mt = 0; mt < 4; mt++) {
            int r0 = wm + mt * 16 + (lane >> 2);
            #pragma unroll
            for (int nt = 0; nt < 4; nt++) {
                int cc = wn + nt * 8 + 2 * (lane & 3);
                uint32_t v0 = pack2(acc[mt][nt][0], acc[mt][nt][1]);
                uint32_t v1 = pack2(acc[mt][nt][2], acc[mt][nt][3]);
                *reinterpret_cast<uint32_t*>(outp + (size_t)r0 * 128 + cc) = v0;
                *reinterpret_cast<uint32_t*>(outp + (size_t)(r0 + 8) * 128 + cc) = v1;
            }
        }
    };

    // ---- initial grab + prologue (stage chunk 0 into stage A) ----
    if (tid == 0) sGrab[0] = atomicAdd(&g_ctr, 1);
    __syncthreads();
    Cur cur;
    if (!decode(cur, sGrab[0])) return;

    uint32_t sA = smb, sB = smb + STAGE_BYTES;
    {
        float wv[16];
        stage_x(sA, cur.xl);
        asm volatile("cp.async.commit_group;");
        // prefetch chunk 1's W while converting chunk 0
        if (cur.nch > 1) {
            const float* pf = cur.wgp + (size_t)(BK + wkb + lane) * A_DIM;
            asm volatile("prefetch.global.L2 [%0];" :: "l"(pf));
        }
        ldg_w(cur.wgp, 0, 0, wv); sts_w(sA, 0, wv);
        ldg_w(cur.wgp, 0, 1, wv); sts_w(sA, 1, wv);
    }
    zero_acc();
    int cloc = 0;

    for (;;) {
        asm volatile("cp.async.wait_group 0;");
        __syncthreads();

        const bool last = (cloc == cur.nch - 1);
        Cur nxt;
        bool nv = false, stg = true;
        const float* swgp = cur.wgp;
        const __half* sxl = cur.xl;
        int skel = (cloc + 1) * BK;
        if (last) {
            nv = decode(nxt, sGrab[0]);
            if (nv) { swgp = nxt.wgp; sxl = nxt.xl; skel = 0; }
            else stg = false;
        }

        float wv[16];
        if (stg) {
            ldg_w(swgp, skel, 0, wv);
            stage_x(sB, sxl + skel);
            // L2 prefetch: chunk c+2's W (full chunk covered once across 256 threads)
            if (cloc + 2 < cur.nch) {
                const float* pf = cur.wgp + (size_t)((cloc + 2) * BK + wkb + lane) * A_DIM;
                asm volatile("prefetch.global.L2 [%0];" :: "l"(pf));
            } else if (last && nv && nxt.nch > 1) {
                const float* pf = nxt.wgp + (size_t)(BK + wkb + lane) * A_DIM;
                asm volatile("prefetch.global.L2 [%0];" :: "l"(pf));
            }
        }
        asm volatile("cp.async.commit_group;");
        compute_kk(sA, 0);
        compute_kk(sA, 1);
        if (stg) { sts_w(sB, 0, wv); ldg_w(swgp, skel, 1, wv); }
        compute_kk(sA, 2);
        compute_kk(sA, 3);
        if (stg) sts_w(sB, 1, wv);

        if (cloc == cur.nch - 2 && tid == 0)
            sGrab[0] = atomicAdd(&g_ctr, 1);

        if (last) {
            epilogue(cur.outp);
            zero_acc();
            if (!nv) break;
            cur = nxt;
            cloc = 0;
        } else {
            cloc++;
        }
        uint32_t t = sA; sA = sB; sB = t;
    }
}

// ---------------- reduction: fp16 partials -> fp32 out, 4 outputs/thread ----------------
__global__ __launch_bounds__(256)
void reduce_kernel(float* __restrict__ out) {
    int idx = blockIdx.x * blockDim.x + threadIdx.x;
    const int total4 = (B_DIM * L_DIM * A_DIM) / 4;
    if (idx >= total4) return;
    int a    = idx * 4;
    int aloc = a & 127;
    int ntc  = (a >> 7) % 6;
    int rem  = idx / (A_DIM / 4);
    int i    = rem % L_DIM;
    int b    = rem / L_DIM;
    int base = i * (i + 1) / 2;

    float4 s = make_float4(0.f, 0.f, 0.f, 0.f);
    for (int l = 0; l <= i; l++) {
        int tile = (base + l) * 6 + ntc;
        if (tile < NFULL_T) {
            uint2 v = *reinterpret_cast<const uint2*>(
                g_s1 + (size_t)tile * 16384 + (size_t)b * 128 + aloc);
            float2 f0 = __half22float2(*reinterpret_cast<__half2*>(&v.x));
            float2 f1 = __half22float2(*reinterpret_cast<__half2*>(&v.y));
            s.x += f0.x; s.y += f0.y; s.z += f1.x; s.w += f1.y;
        } else {
            const __half* pb = g_s2 + (size_t)(tile - NFULL_T) * 4 * 16384
                             + (size_t)b * 128 + aloc;
            #pragma unroll
            for (int q = 0; q < 4; q++) {
                uint2 v = *reinterpret_cast<const uint2*>(pb + (size_t)q * 16384);
                float2 f0 = __half22float2(*reinterpret_cast<__half2*>(&v.x));
                float2 f1 = __half22float2(*reinterpret_cast<__half2*>(&v.y));
                s.x += f0.x; s.y += f0.y; s.z += f1.x; s.w += f1.y;
            }
        }
    }
    size_t flat = ((size_t)b * L_DIM + i) * A_DIM + (a % A_DIM);
    *reinterpret_cast<float4*>(out + flat) = s;
}

extern "C" void kernel_launch(void* const* d_in, const int* in_sizes, int n_in,
                              void* d_out, int out_size) {
    const float* x = (const float*)d_in[0];
    WPtrs wp;
    for (int i = 0; i < 12; i++) wp.w[i] = (const float*)d_in[1 + i];

    int dev = 0;
    cudaGetDevice(&dev);
    int sms = 0;
    cudaDeviceGetAttribute(&sms, cudaDevAttrMultiProcessorCount, dev);
    int G = 2 * sms;
    if (G > NFULL_T) G = NFULL_T;
    if (G < 1) G = 1;

    cudaFuncSetAttribute(reinterpret_cast<const void*>(gemm_pair_kernel),
                         cudaFuncAttributeMaxDynamicSharedMemorySize, SMEM_BYTES);

    const int n8 = (B_DIM * L_DIM * F_DIM) / 8;
    cvt_x_kernel<<<(n8 + 255) / 256, 256>>>(x);

    gemm_pair_kernel<<<G, THREADS, SMEM_BYTES>>>(wp);

    const int total4 = (B_DIM * L_DIM * A_DIM) / 4;
    reduce_kernel<<<(total4 + 255) / 256, 256>>>((float*)d_out);
}